// round 4
// baseline (speedup 1.0000x reference)
#include <cuda_runtime.h>
#include <cstdint>
#include <cstddef>

// ---------------------------------------------------------------------------
// corr_net: 3x conv1x1 (batched GEMM) -> Gram-matrix correlation -> fused
// gather+leaky+conv3x3 corr head -> direct conv3x3 cat head -> MLPs -> out.
//
// Shapes: B=128, C=512, H=10, W=20 (200 px), MD=20, S2=2 (441 displacements,
// of which exactly 5x10=50 are in-range per pixel).
// ---------------------------------------------------------------------------

#define NPIX 200

// ---------------- scratch (static device globals; no allocations) ----------
__device__ float g_WT[3 * 512 * 512];            //   3 MB  transposed 1x1 weights
__device__ float g_feat[3 * 128 * 512 * 200];    // 157 MB  f1,f2,f3 (post conv1x1)
__device__ float g_gram[3 * 128 * 200 * 200];    //  61 MB  Gram per (pair,batch)
__device__ float g_corrvec[128 * 600];
__device__ float g_catvec[128 * 600];

// ---------------- transpose the three 512x512 weight matrices --------------
__global__ void transpose3_kernel(const float* __restrict__ Wa,
                                  const float* __restrict__ Wb,
                                  const float* __restrict__ Wc,
                                  float* __restrict__ WT)
{
    int idx = blockIdx.x * 256 + threadIdx.x;   // grid sized exactly
    int t = idx >> 18;
    int r = idx & 262143;
    int k = r >> 9, m = r & 511;
    const float* Wsrc = (t == 0) ? Wa : ((t == 1) ? Wb : Wc);
    WT[idx] = Wsrc[m * 512 + k];                // WT[t][k*512+m] = W[m][k]
}

// ---------------- generic K-major batched GEMM ------------------------------
// C[m,n] = sum_k A[k*lda+m] * B[k*ldb+n]  (+ bias[m])
// Tile 128x128, BK=16, 256 threads, 8x8 per thread, all float4 aligned.
template <bool BIAS>
__global__ __launch_bounds__(256)
void gemm_ta_kernel(const float* __restrict__ A, size_t strideA,
                    const float* __restrict__ B, size_t strideB,
                    float* __restrict__ C, size_t strideC,
                    const float* __restrict__ bias,
                    int M, int N, int K, int lda, int ldb, int ldc)
{
    __shared__ float As[16][128];
    __shared__ float Bs[16][128];
    const int tid = threadIdx.x;
    const int tx = tid & 15, ty = tid >> 4;
    const int m0 = blockIdx.y * 128, n0 = blockIdx.x * 128;
    A += strideA * blockIdx.z;
    B += strideB * blockIdx.z;
    C += strideC * blockIdx.z;

    float acc[8][8];
#pragma unroll
    for (int i = 0; i < 8; i++)
#pragma unroll
        for (int j = 0; j < 8; j++) acc[i][j] = 0.f;

    for (int k0 = 0; k0 < K; k0 += 16) {
#pragma unroll
        for (int i = 0; i < 2; i++) {
            int f = tid + i * 256;              // 0..511 float4 slots
            int kk = f >> 5;
            int c4 = (f & 31) << 2;
            float4 av = make_float4(0.f, 0.f, 0.f, 0.f);
            if (m0 + c4 < M)
                av = *reinterpret_cast<const float4*>(A + (size_t)(k0 + kk) * lda + m0 + c4);
            *reinterpret_cast<float4*>(&As[kk][c4]) = av;
            float4 bv = make_float4(0.f, 0.f, 0.f, 0.f);
            if (n0 + c4 < N)
                bv = *reinterpret_cast<const float4*>(B + (size_t)(k0 + kk) * ldb + n0 + c4);
            *reinterpret_cast<float4*>(&Bs[kk][c4]) = bv;
        }
        __syncthreads();
#pragma unroll
        for (int kk = 0; kk < 16; kk++) {
            float4 a0 = *reinterpret_cast<const float4*>(&As[kk][ty * 8]);
            float4 a1 = *reinterpret_cast<const float4*>(&As[kk][ty * 8 + 4]);
            float4 b0 = *reinterpret_cast<const float4*>(&Bs[kk][tx * 4]);
            float4 b1 = *reinterpret_cast<const float4*>(&Bs[kk][64 + tx * 4]);
            float a[8] = {a0.x, a0.y, a0.z, a0.w, a1.x, a1.y, a1.z, a1.w};
            float bb[8] = {b0.x, b0.y, b0.z, b0.w, b1.x, b1.y, b1.z, b1.w};
#pragma unroll
            for (int i = 0; i < 8; i++)
#pragma unroll
                for (int j = 0; j < 8; j++) acc[i][j] += a[i] * bb[j];
        }
        __syncthreads();
    }
#pragma unroll
    for (int i = 0; i < 8; i++) {
        int gm = m0 + ty * 8 + i;
        if (gm >= M) continue;
        float bv = BIAS ? bias[gm] : 0.f;
        int gn = n0 + tx * 4;
        if (gn < N) {
            float4 v = make_float4(acc[i][0] + bv, acc[i][1] + bv,
                                   acc[i][2] + bv, acc[i][3] + bv);
            *reinterpret_cast<float4*>(C + (size_t)gm * ldc + gn) = v;
        }
        gn += 64;
        if (gn < N) {
            float4 v = make_float4(acc[i][4] + bv, acc[i][5] + bv,
                                   acc[i][6] + bv, acc[i][7] + bv);
            *reinterpret_cast<float4*>(C + (size_t)gm * ldc + gn) = v;
        }
    }
}

// ---------------- corr head: gather from Gram + leaky + conv3x3 + relu ------
// One block per batch. Gram tile (160KB) + per-pair weights (47.6KB) in smem.
// For source pixel (sy,sx): valid dyi = [(21-sy)>>1, +5), valid dxi = [(21-sx)>>1, +10).
__global__ __launch_bounds__(256)
void corr_head_kernel(const float* __restrict__ Gram,
                      const float* __restrict__ Wcorr,
                      const float* __restrict__ bcorr,
                      float* __restrict__ corrvec)
{
    extern __shared__ float sh[];
    float* sG = sh;             // 40000 floats
    float* sW = sh + 40000;     // 11907 floats: [o][d][tap] for current pair
    const int b = blockIdx.x;
    const int tid = threadIdx.x;
    const int y = tid / 20, x = tid - y * 20;
    float acc0 = 0.f, acc1 = 0.f, acc2 = 0.f;

    for (int pair = 0; pair < 3; pair++) {
        __syncthreads();
        const float4* G4 = reinterpret_cast<const float4*>(Gram + ((size_t)pair * 128 + b) * 40000);
        float4* sG4 = reinterpret_cast<float4*>(sG);
        for (int i = tid; i < 10000; i += 256) sG4[i] = G4[i];
        for (int i = tid; i < 11907; i += 256) {
            int o = i / 3969, r = i - o * 3969;
            sW[i] = Wcorr[o * 11907 + pair * 3969 + r];
        }
        __syncthreads();

        if (tid < NPIX) {
            for (int ky = 0; ky < 3; ky++) {
                int sy = y + ky - 1;
                if ((unsigned)sy >= 10u) continue;
                for (int kx = 0; kx < 3; kx++) {
                    int sx = x + kx - 1;
                    if ((unsigned)sx >= 20u) continue;
                    const float* grow0 = sG + (sy * 20 + sx) * 200;
                    const int tap = ky * 3 + kx;
                    const int dyi0 = (21 - sy) >> 1;
                    const int dxi0 = (21 - sx) >> 1;
                    const int p2y0 = sy + 2 * dyi0 - 20;
                    const int p2x0 = sx + 2 * dxi0 - 20;
                    for (int iy = 0; iy < 5; iy++) {
                        const float* grow = grow0 + (p2y0 + 2 * iy) * 20 + p2x0;
                        const float* wrow = sW + ((dyi0 + iy) * 21 + dxi0) * 9 + tap;
#pragma unroll
                        for (int ix = 0; ix < 10; ix++) {
                            float g = grow[2 * ix] * (1.f / 512.f);
                            float v = g > 0.f ? g : 0.1f * g;   // leaky relu 0.1
                            acc0 += v * wrow[ix * 9];
                            acc1 += v * wrow[3969 + ix * 9];
                            acc2 += v * wrow[7938 + ix * 9];
                        }
                    }
                }
            }
        }
    }
    if (tid < NPIX) {
        corrvec[b * 600 + tid]       = fmaxf(acc0 + bcorr[0], 0.f);
        corrvec[b * 600 + 200 + tid] = fmaxf(acc1 + bcorr[1], 0.f);
        corrvec[b * 600 + 400 + tid] = fmaxf(acc2 + bcorr[2], 0.f);
    }
}

// ---------------- cat head: conv3x3 over concat(f1,f2,f3), no relu ----------
// One block per batch; channel chunks of 64 in smem, channel-major layout
// (pad 68) so per-pixel inner product vectorizes as float4 dot products.
__global__ __launch_bounds__(256)
void cat_head_kernel(const float* __restrict__ F,     // g_feat: [3][128][512][200]
                     const float* __restrict__ Wcat,  // [3][1536][3][3]
                     const float* __restrict__ bcat,
                     float* __restrict__ catvec)
{
    extern __shared__ float sh[];
    float* sF = sh;             // 3*200*68 = 40800 floats, layout [(t*200+p)*68 + c]
    float* sW = sh + 40800;     // 5184: [((o*3+t)*9+tap)*64 + c]
    const int b = blockIdx.x;
    const int tid = threadIdx.x;
    const int y = tid / 20, x = tid - y * 20;
    float acc0 = 0.f, acc1 = 0.f, acc2 = 0.f;

    for (int cc = 0; cc < 512; cc += 64) {
        __syncthreads();
        for (int e = tid; e < 38400; e += 256) {
            int t = e / 12800;
            int r = e - t * 12800;
            int c = r / 200;
            int p = r - c * 200;
            sF[(t * 200 + p) * 68 + c] =
                F[(size_t)t * 13107200 + (size_t)b * 102400 + (size_t)(cc + c) * 200 + p];
        }
        for (int i = tid; i < 5184; i += 256) {
            int o = i / 1728;
            int r = i - o * 1728;
            int t = r / 576;
            int r2 = r - t * 576;
            int tap = r2 >> 6;
            int c = r2 & 63;
            sW[i] = Wcat[(size_t)(o * 1536 + t * 512 + cc + c) * 9 + tap];
        }
        __syncthreads();

        if (tid < NPIX) {
            for (int t = 0; t < 3; t++) {
                for (int ky = 0; ky < 3; ky++) {
                    int sy = y + ky - 1;
                    if ((unsigned)sy >= 10u) continue;
                    for (int kx = 0; kx < 3; kx++) {
                        int sx = x + kx - 1;
                        if ((unsigned)sx >= 20u) continue;
                        const float4* v4 =
                            reinterpret_cast<const float4*>(sF + (t * 200 + sy * 20 + sx) * 68);
                        int tap = ky * 3 + kx;
                        const float4* w0 = reinterpret_cast<const float4*>(sW + (t * 9 + tap) * 64);
                        const float4* w1 = reinterpret_cast<const float4*>(sW + 1728 + (t * 9 + tap) * 64);
                        const float4* w2 = reinterpret_cast<const float4*>(sW + 3456 + (t * 9 + tap) * 64);
#pragma unroll
                        for (int c4 = 0; c4 < 16; c4++) {
                            float4 v = v4[c4];
                            float4 a = w0[c4], bq = w1[c4], cq = w2[c4];
                            acc0 += v.x * a.x + v.y * a.y + v.z * a.z + v.w * a.w;
                            acc1 += v.x * bq.x + v.y * bq.y + v.z * bq.z + v.w * bq.w;
                            acc2 += v.x * cq.x + v.y * cq.y + v.z * cq.z + v.w * cq.w;
                        }
                    }
                }
            }
        }
    }
    if (tid < NPIX) {
        catvec[b * 600 + tid]       = acc0 + bcat[0];   // no relu (per reference)
        catvec[b * 600 + 200 + tid] = acc1 + bcat[1];
        catvec[b * 600 + 400 + tid] = acc2 + bcat[2];
    }
}

// ---------------- two MLP paths + final linear ------------------------------
__global__ __launch_bounds__(256)
void mlp_kernel(const float* __restrict__ corrvec, const float* __restrict__ catvec,
                const float* __restrict__ cf_w1, const float* __restrict__ cf_b1,
                const float* __restrict__ cf_w2, const float* __restrict__ cf_b2,
                const float* __restrict__ ccf_w1, const float* __restrict__ ccf_b1,
                const float* __restrict__ ccf_w2, const float* __restrict__ ccf_b2,
                const float* __restrict__ Wout, const float* __restrict__ bout,
                float* __restrict__ out)
{
    __shared__ float sx[600];
    __shared__ float h1[256];
    __shared__ float h2[2][128];
    const int b = blockIdx.x, tid = threadIdx.x;

    for (int path = 0; path < 2; path++) {
        const float* xv = (path == 0 ? corrvec : catvec) + b * 600;
        const float* w1 = path == 0 ? cf_w1 : ccf_w1;
        const float* b1 = path == 0 ? cf_b1 : ccf_b1;
        const float* w2 = path == 0 ? cf_w2 : ccf_w2;
        const float* b2 = path == 0 ? cf_b2 : ccf_b2;
        __syncthreads();
        for (int i = tid; i < 600; i += 256) sx[i] = xv[i];
        __syncthreads();
        {
            float s = b1[tid];
            const float4* wr = reinterpret_cast<const float4*>(w1 + (size_t)tid * 600);
#pragma unroll 4
            for (int k = 0; k < 150; k++) {
                float4 w = wr[k];
                s += w.x * sx[4 * k] + w.y * sx[4 * k + 1] + w.z * sx[4 * k + 2] + w.w * sx[4 * k + 3];
            }
            h1[tid] = fmaxf(s, 0.f);
        }
        __syncthreads();
        if (tid < 128) {
            float s = b2[tid];
            const float4* wr = reinterpret_cast<const float4*>(w2 + (size_t)tid * 256);
#pragma unroll 4
            for (int k = 0; k < 64; k++) {
                float4 w = wr[k];
                s += w.x * h1[4 * k] + w.y * h1[4 * k + 1] + w.z * h1[4 * k + 2] + w.w * h1[4 * k + 3];
            }
            h2[path][tid] = fmaxf(s, 0.f);
        }
    }
    __syncthreads();
    if (tid < 2) {
        float s = bout[tid];
        const float* wr = Wout + tid * 256;
        for (int i = 0; i < 128; i++)
            s += h2[0][i] * wr[i] + h2[1][i] * wr[128 + i];
        out[b * 2 + tid] = s;
    }
}

// ---------------- launch ----------------------------------------------------
extern "C" void kernel_launch(void* const* d_in, const int* in_sizes, int n_in,
                              void* d_out, int out_size)
{
    (void)in_sizes; (void)n_in; (void)out_size;
    const float* feat1 = (const float*)d_in[0];
    const float* feat2 = (const float*)d_in[1];
    const float* feat3 = (const float*)d_in[2];
    const float* Wa = (const float*)d_in[3];   const float* ba = (const float*)d_in[4];
    const float* Wb = (const float*)d_in[5];   const float* bb = (const float*)d_in[6];
    const float* Wc = (const float*)d_in[7];   const float* bc = (const float*)d_in[8];
    const float* Wcorr = (const float*)d_in[9];  const float* bcorr = (const float*)d_in[10];
    const float* Wcat = (const float*)d_in[11];  const float* bcat = (const float*)d_in[12];
    const float* cf_w1 = (const float*)d_in[13]; const float* cf_b1 = (const float*)d_in[14];
    const float* cf_w2 = (const float*)d_in[15]; const float* cf_b2 = (const float*)d_in[16];
    const float* ccf_w1 = (const float*)d_in[17]; const float* ccf_b1 = (const float*)d_in[18];
    const float* ccf_w2 = (const float*)d_in[19]; const float* ccf_b2 = (const float*)d_in[20];
    const float* Wout = (const float*)d_in[21];  const float* bout = (const float*)d_in[22];

    float *WT, *F, *G, *cv, *tv;
    cudaGetSymbolAddress((void**)&WT, g_WT);
    cudaGetSymbolAddress((void**)&F,  g_feat);
    cudaGetSymbolAddress((void**)&G,  g_gram);
    cudaGetSymbolAddress((void**)&cv, g_corrvec);
    cudaGetSymbolAddress((void**)&tv, g_catvec);

    // 1) transpose the 1x1 conv weights (so GEMM always reads K-major A)
    transpose3_kernel<<<3 * 512 * 512 / 256, 256>>>(Wa, Wb, Wc, WT);

    // 2) conv1x1 x3: F[t][b] (512x200) = WT[t]^T-applied GEMM + bias
    const float* feats[3]  = {feat1, feat2, feat3};
    const float* biases[3] = {ba, bb, bc};
    dim3 gridConv(2, 4, 128);   // N=200 -> 2 tiles, M=512 -> 4 tiles
    for (int t = 0; t < 3; t++) {
        gemm_ta_kernel<true><<<gridConv, 256>>>(
            WT + (size_t)t * 262144, 0,
            feats[t], 102400,
            F + (size_t)t * 13107200, 102400,
            biases[t], 512, 200, 512, 512, 200, 200);
    }

    // 3) Gram matrices per pair: G[pair][b] = f_a^T f_b  (200x200, K=512)
    dim3 gridGram(2, 2, 128);
    const int pa[3] = {0, 0, 1}, pb[3] = {1, 2, 2};
    for (int p = 0; p < 3; p++) {
        gemm_ta_kernel<false><<<gridGram, 256>>>(
            F + (size_t)pa[p] * 13107200, 102400,
            F + (size_t)pb[p] * 13107200, 102400,
            G + (size_t)p * 128 * 40000, 40000,
            nullptr, 200, 200, 512, 200, 200, 200);
    }

    // 4) fused correlation gather + leaky + conv3x3 + relu
    const int CORR_SMEM = (40000 + 11907) * 4;   // 207628 B
    cudaFuncSetAttribute(corr_head_kernel, cudaFuncAttributeMaxDynamicSharedMemorySize, CORR_SMEM);
    corr_head_kernel<<<128, 256, CORR_SMEM>>>(G, Wcorr, bcorr, cv);

    // 5) cat conv3x3
    const int CAT_SMEM = (40800 + 5184) * 4;     // 183936 B
    cudaFuncSetAttribute(cat_head_kernel, cudaFuncAttributeMaxDynamicSharedMemorySize, CAT_SMEM);
    cat_head_kernel<<<128, 256, CAT_SMEM>>>(F, Wcat, bcat, tv);

    // 6) MLP heads + final linear -> [128,2]
    mlp_kernel<<<128, 256>>>(cv, tv, cf_w1, cf_b1, cf_w2, cf_b2,
                             ccf_w1, ccf_b1, ccf_w2, ccf_b2,
                             Wout, bout, (float*)d_out);
}

// round 5
// speedup vs baseline: 1.0063x; 1.0063x over previous
#include <cuda_runtime.h>
#include <cstdint>
#include <cstddef>

// ---------------------------------------------------------------------------
// corr_net: 3x conv1x1 (batched GEMM) -> Gram-matrix correlation -> fused
// gather+leaky+conv3x3 corr head -> direct conv3x3 cat head -> MLPs -> out.
//
// Shapes: B=128, C=512, H=10, W=20 (200 px), MD=20, S2=2 (441 displacements,
// of which exactly 5x10=50 are in-range per pixel).
// ---------------------------------------------------------------------------

#define NPIX 200

// ---------------- scratch (static device globals; no allocations) ----------
__device__ float g_WT[3 * 512 * 512];            //   3 MB  transposed 1x1 weights
__device__ float g_feat[3 * 128 * 512 * 200];    // 157 MB  f1,f2,f3 (post conv1x1)
__device__ float g_gram[3 * 128 * 200 * 200];    //  61 MB  Gram per (pair,batch)
__device__ float g_corrvec[128 * 600];
__device__ float g_catvec[128 * 600];

// ---------------- transpose the three 512x512 weight matrices --------------
__global__ void transpose3_kernel(const float* __restrict__ Wa,
                                  const float* __restrict__ Wb,
                                  const float* __restrict__ Wc,
                                  float* __restrict__ WT)
{
    int idx = blockIdx.x * 256 + threadIdx.x;   // grid sized exactly
    int t = idx >> 18;
    int r = idx & 262143;
    int k = r >> 9, m = r & 511;
    const float* Wsrc = (t == 0) ? Wa : ((t == 1) ? Wb : Wc);
    WT[idx] = Wsrc[m * 512 + k];                // WT[t][k*512+m] = W[m][k]
}

// ---------------- generic K-major batched GEMM ------------------------------
// C[m,n] = sum_k A[k*lda+m] * B[k*ldb+n]  (+ bias[m])
// Tile 128x128, BK=16, 256 threads, 8x8 per thread, all float4 aligned.
template <bool BIAS>
__global__ __launch_bounds__(256)
void gemm_ta_kernel(const float* __restrict__ A, size_t strideA,
                    const float* __restrict__ B, size_t strideB,
                    float* __restrict__ C, size_t strideC,
                    const float* __restrict__ bias,
                    int M, int N, int K, int lda, int ldb, int ldc)
{
    __shared__ float As[16][128];
    __shared__ float Bs[16][128];
    const int tid = threadIdx.x;
    const int tx = tid & 15, ty = tid >> 4;
    const int m0 = blockIdx.y * 128, n0 = blockIdx.x * 128;
    A += strideA * blockIdx.z;
    B += strideB * blockIdx.z;
    C += strideC * blockIdx.z;

    float acc[8][8];
#pragma unroll
    for (int i = 0; i < 8; i++)
#pragma unroll
        for (int j = 0; j < 8; j++) acc[i][j] = 0.f;

    for (int k0 = 0; k0 < K; k0 += 16) {
#pragma unroll
        for (int i = 0; i < 2; i++) {
            int f = tid + i * 256;              // 0..511 float4 slots
            int kk = f >> 5;
            int c4 = (f & 31) << 2;
            float4 av = make_float4(0.f, 0.f, 0.f, 0.f);
            if (m0 + c4 < M)
                av = *reinterpret_cast<const float4*>(A + (size_t)(k0 + kk) * lda + m0 + c4);
            *reinterpret_cast<float4*>(&As[kk][c4]) = av;
            float4 bv = make_float4(0.f, 0.f, 0.f, 0.f);
            if (n0 + c4 < N)
                bv = *reinterpret_cast<const float4*>(B + (size_t)(k0 + kk) * ldb + n0 + c4);
            *reinterpret_cast<float4*>(&Bs[kk][c4]) = bv;
        }
        __syncthreads();
#pragma unroll
        for (int kk = 0; kk < 16; kk++) {
            float4 a0 = *reinterpret_cast<const float4*>(&As[kk][ty * 8]);
            float4 a1 = *reinterpret_cast<const float4*>(&As[kk][ty * 8 + 4]);
            float4 b0 = *reinterpret_cast<const float4*>(&Bs[kk][tx * 4]);
            float4 b1 = *reinterpret_cast<const float4*>(&Bs[kk][64 + tx * 4]);
            float a[8] = {a0.x, a0.y, a0.z, a0.w, a1.x, a1.y, a1.z, a1.w};
            float bb[8] = {b0.x, b0.y, b0.z, b0.w, b1.x, b1.y, b1.z, b1.w};
#pragma unroll
            for (int i = 0; i < 8; i++)
#pragma unroll
                for (int j = 0; j < 8; j++) acc[i][j] += a[i] * bb[j];
        }
        __syncthreads();
    }
#pragma unroll
    for (int i = 0; i < 8; i++) {
        int gm = m0 + ty * 8 + i;
        if (gm >= M) continue;
        float bv = BIAS ? bias[gm] : 0.f;
        int gn = n0 + tx * 4;
        if (gn < N) {
            float4 v = make_float4(acc[i][0] + bv, acc[i][1] + bv,
                                   acc[i][2] + bv, acc[i][3] + bv);
            *reinterpret_cast<float4*>(C + (size_t)gm * ldc + gn) = v;
        }
        gn += 64;
        if (gn < N) {
            float4 v = make_float4(acc[i][4] + bv, acc[i][5] + bv,
                                   acc[i][6] + bv, acc[i][7] + bv);
            *reinterpret_cast<float4*>(C + (size_t)gm * ldc + gn) = v;
        }
    }
}

// ---------------- corr head: gather from Gram + leaky + conv3x3 + relu ------
// One block per batch. Gram tile (160KB) + per-pair weights (47.6KB) in smem.
// For source pixel (sy,sx): valid dyi = [(21-sy)>>1, +5), valid dxi = [(21-sx)>>1, +10).
__global__ __launch_bounds__(256)
void corr_head_kernel(const float* __restrict__ Gram,
                      const float* __restrict__ Wcorr,
                      const float* __restrict__ bcorr,
                      float* __restrict__ corrvec)
{
    extern __shared__ float sh[];
    float* sG = sh;             // 40000 floats
    float* sW = sh + 40000;     // 11907 floats: [o][d][tap] for current pair
    const int b = blockIdx.x;
    const int tid = threadIdx.x;
    const int y = tid / 20, x = tid - y * 20;
    float acc0 = 0.f, acc1 = 0.f, acc2 = 0.f;

    for (int pair = 0; pair < 3; pair++) {
        __syncthreads();
        const float4* G4 = reinterpret_cast<const float4*>(Gram + ((size_t)pair * 128 + b) * 40000);
        float4* sG4 = reinterpret_cast<float4*>(sG);
        for (int i = tid; i < 10000; i += 256) sG4[i] = G4[i];
        for (int i = tid; i < 11907; i += 256) {
            int o = i / 3969, r = i - o * 3969;
            sW[i] = Wcorr[o * 11907 + pair * 3969 + r];
        }
        __syncthreads();

        if (tid < NPIX) {
            for (int ky = 0; ky < 3; ky++) {
                int sy = y + ky - 1;
                if ((unsigned)sy >= 10u) continue;
                for (int kx = 0; kx < 3; kx++) {
                    int sx = x + kx - 1;
                    if ((unsigned)sx >= 20u) continue;
                    const float* grow0 = sG + (sy * 20 + sx) * 200;
                    const int tap = ky * 3 + kx;
                    const int dyi0 = (21 - sy) >> 1;
                    const int dxi0 = (21 - sx) >> 1;
                    const int p2y0 = sy + 2 * dyi0 - 20;
                    const int p2x0 = sx + 2 * dxi0 - 20;
                    for (int iy = 0; iy < 5; iy++) {
                        const float* grow = grow0 + (p2y0 + 2 * iy) * 20 + p2x0;
                        const float* wrow = sW + ((dyi0 + iy) * 21 + dxi0) * 9 + tap;
#pragma unroll
                        for (int ix = 0; ix < 10; ix++) {
                            float g = grow[2 * ix] * (1.f / 512.f);
                            float v = g > 0.f ? g : 0.1f * g;   // leaky relu 0.1
                            acc0 += v * wrow[ix * 9];
                            acc1 += v * wrow[3969 + ix * 9];
                            acc2 += v * wrow[7938 + ix * 9];
                        }
                    }
                }
            }
        }
    }
    if (tid < NPIX) {
        corrvec[b * 600 + tid]       = fmaxf(acc0 + bcorr[0], 0.f);
        corrvec[b * 600 + 200 + tid] = fmaxf(acc1 + bcorr[1], 0.f);
        corrvec[b * 600 + 400 + tid] = fmaxf(acc2 + bcorr[2], 0.f);
    }
}

// ---------------- cat head: conv3x3 over concat(f1,f2,f3), no relu ----------
// One block per batch; channel chunks of 64 in smem, channel-major layout
// (pad 68) so per-pixel inner product vectorizes as float4 dot products.
__global__ __launch_bounds__(256)
void cat_head_kernel(const float* __restrict__ F,     // g_feat: [3][128][512][200]
                     const float* __restrict__ Wcat,  // [3][1536][3][3]
                     const float* __restrict__ bcat,
                     float* __restrict__ catvec)
{
    extern __shared__ float sh[];
    float* sF = sh;             // 3*200*68 = 40800 floats, layout [(t*200+p)*68 + c]
    float* sW = sh + 40800;     // 5184: [((o*3+t)*9+tap)*64 + c]
    const int b = blockIdx.x;
    const int tid = threadIdx.x;
    const int y = tid / 20, x = tid - y * 20;
    float acc0 = 0.f, acc1 = 0.f, acc2 = 0.f;

    for (int cc = 0; cc < 512; cc += 64) {
        __syncthreads();
        for (int e = tid; e < 38400; e += 256) {
            int t = e / 12800;
            int r = e - t * 12800;
            int c = r / 200;
            int p = r - c * 200;
            sF[(t * 200 + p) * 68 + c] =
                F[(size_t)t * 13107200 + (size_t)b * 102400 + (size_t)(cc + c) * 200 + p];
        }
        for (int i = tid; i < 5184; i += 256) {
            int o = i / 1728;
            int r = i - o * 1728;
            int t = r / 576;
            int r2 = r - t * 576;
            int tap = r2 >> 6;
            int c = r2 & 63;
            sW[i] = Wcat[(size_t)(o * 1536 + t * 512 + cc + c) * 9 + tap];
        }
        __syncthreads();

        if (tid < NPIX) {
            for (int t = 0; t < 3; t++) {
                for (int ky = 0; ky < 3; ky++) {
                    int sy = y + ky - 1;
                    if ((unsigned)sy >= 10u) continue;
                    for (int kx = 0; kx < 3; kx++) {
                        int sx = x + kx - 1;
                        if ((unsigned)sx >= 20u) continue;
                        const float4* v4 =
                            reinterpret_cast<const float4*>(sF + (t * 200 + sy * 20 + sx) * 68);
                        int tap = ky * 3 + kx;
                        const float4* w0 = reinterpret_cast<const float4*>(sW + (t * 9 + tap) * 64);
                        const float4* w1 = reinterpret_cast<const float4*>(sW + 1728 + (t * 9 + tap) * 64);
                        const float4* w2 = reinterpret_cast<const float4*>(sW + 3456 + (t * 9 + tap) * 64);
#pragma unroll
                        for (int c4 = 0; c4 < 16; c4++) {
                            float4 v = v4[c4];
                            float4 a = w0[c4], bq = w1[c4], cq = w2[c4];
                            acc0 += v.x * a.x + v.y * a.y + v.z * a.z + v.w * a.w;
                            acc1 += v.x * bq.x + v.y * bq.y + v.z * bq.z + v.w * bq.w;
                            acc2 += v.x * cq.x + v.y * cq.y + v.z * cq.z + v.w * cq.w;
                        }
                    }
                }
            }
        }
    }
    if (tid < NPIX) {
        catvec[b * 600 + tid]       = acc0 + bcat[0];   // no relu (per reference)
        catvec[b * 600 + 200 + tid] = acc1 + bcat[1];
        catvec[b * 600 + 400 + tid] = acc2 + bcat[2];
    }
}

// ---------------- two MLP paths + final linear ------------------------------
__global__ __launch_bounds__(256)
void mlp_kernel(const float* __restrict__ corrvec, const float* __restrict__ catvec,
                const float* __restrict__ cf_w1, const float* __restrict__ cf_b1,
                const float* __restrict__ cf_w2, const float* __restrict__ cf_b2,
                const float* __restrict__ ccf_w1, const float* __restrict__ ccf_b1,
                const float* __restrict__ ccf_w2, const float* __restrict__ ccf_b2,
                const float* __restrict__ Wout, const float* __restrict__ bout,
                float* __restrict__ out)
{
    __shared__ float sx[600];
    __shared__ float h1[256];
    __shared__ float h2[2][128];
    const int b = blockIdx.x, tid = threadIdx.x;

    for (int path = 0; path < 2; path++) {
        const float* xv = (path == 0 ? corrvec : catvec) + b * 600;
        const float* w1 = path == 0 ? cf_w1 : ccf_w1;
        const float* b1 = path == 0 ? cf_b1 : ccf_b1;
        const float* w2 = path == 0 ? cf_w2 : ccf_w2;
        const float* b2 = path == 0 ? cf_b2 : ccf_b2;
        __syncthreads();
        for (int i = tid; i < 600; i += 256) sx[i] = xv[i];
        __syncthreads();
        {
            float s = b1[tid];
            const float4* wr = reinterpret_cast<const float4*>(w1 + (size_t)tid * 600);
#pragma unroll 4
            for (int k = 0; k < 150; k++) {
                float4 w = wr[k];
                s += w.x * sx[4 * k] + w.y * sx[4 * k + 1] + w.z * sx[4 * k + 2] + w.w * sx[4 * k + 3];
            }
            h1[tid] = fmaxf(s, 0.f);
        }
        __syncthreads();
        if (tid < 128) {
            float s = b2[tid];
            const float4* wr = reinterpret_cast<const float4*>(w2 + (size_t)tid * 256);
#pragma unroll 4
            for (int k = 0; k < 64; k++) {
                float4 w = wr[k];
                s += w.x * h1[4 * k] + w.y * h1[4 * k + 1] + w.z * h1[4 * k + 2] + w.w * h1[4 * k + 3];
            }
            h2[path][tid] = fmaxf(s, 0.f);
        }
    }
    __syncthreads();
    if (tid < 2) {
        float s = bout[tid];
        const float* wr = Wout + tid * 256;
        for (int i = 0; i < 128; i++)
            s += h2[0][i] * wr[i] + h2[1][i] * wr[128 + i];
        out[b * 2 + tid] = s;
    }
}

// ---------------- launch ----------------------------------------------------
extern "C" void kernel_launch(void* const* d_in, const int* in_sizes, int n_in,
                              void* d_out, int out_size)
{
    (void)in_sizes; (void)n_in; (void)out_size;
    const float* feat1 = (const float*)d_in[0];
    const float* feat2 = (const float*)d_in[1];
    const float* feat3 = (const float*)d_in[2];
    const float* Wa = (const float*)d_in[3];   const float* ba = (const float*)d_in[4];
    const float* Wb = (const float*)d_in[5];   const float* bb = (const float*)d_in[6];
    const float* Wc = (const float*)d_in[7];   const float* bc = (const float*)d_in[8];
    const float* Wcorr = (const float*)d_in[9];  const float* bcorr = (const float*)d_in[10];
    const float* Wcat = (const float*)d_in[11];  const float* bcat = (const float*)d_in[12];
    const float* cf_w1 = (const float*)d_in[13]; const float* cf_b1 = (const float*)d_in[14];
    const float* cf_w2 = (const float*)d_in[15]; const float* cf_b2 = (const float*)d_in[16];
    const float* ccf_w1 = (const float*)d_in[17]; const float* ccf_b1 = (const float*)d_in[18];
    const float* ccf_w2 = (const float*)d_in[19]; const float* ccf_b2 = (const float*)d_in[20];
    const float* Wout = (const float*)d_in[21];  const float* bout = (const float*)d_in[22];

    float *WT, *F, *G, *cv, *tv;
    cudaGetSymbolAddress((void**)&WT, g_WT);
    cudaGetSymbolAddress((void**)&F,  g_feat);
    cudaGetSymbolAddress((void**)&G,  g_gram);
    cudaGetSymbolAddress((void**)&cv, g_corrvec);
    cudaGetSymbolAddress((void**)&tv, g_catvec);

    // 1) transpose the 1x1 conv weights (so GEMM always reads K-major A)
    transpose3_kernel<<<3 * 512 * 512 / 256, 256>>>(Wa, Wb, Wc, WT);

    // 2) conv1x1 x3: F[t][b] (512x200) = WT[t]^T-applied GEMM + bias
    const float* feats[3]  = {feat1, feat2, feat3};
    const float* biases[3] = {ba, bb, bc};
    dim3 gridConv(2, 4, 128);   // N=200 -> 2 tiles, M=512 -> 4 tiles
    for (int t = 0; t < 3; t++) {
        gemm_ta_kernel<true><<<gridConv, 256>>>(
            WT + (size_t)t * 262144, 0,
            feats[t], 102400,
            F + (size_t)t * 13107200, 102400,
            biases[t], 512, 200, 512, 512, 200, 200);
    }

    // 3) Gram matrices per pair: G[pair][b] = f_a^T f_b  (200x200, K=512)
    dim3 gridGram(2, 2, 128);
    const int pa[3] = {0, 0, 1}, pb[3] = {1, 2, 2};
    for (int p = 0; p < 3; p++) {
        gemm_ta_kernel<false><<<gridGram, 256>>>(
            F + (size_t)pa[p] * 13107200, 102400,
            F + (size_t)pb[p] * 13107200, 102400,
            G + (size_t)p * 128 * 40000, 40000,
            nullptr, 200, 200, 512, 200, 200, 200);
    }

    // 4) fused correlation gather + leaky + conv3x3 + relu
    const int CORR_SMEM = (40000 + 11907) * 4;   // 207628 B
    cudaFuncSetAttribute(corr_head_kernel, cudaFuncAttributeMaxDynamicSharedMemorySize, CORR_SMEM);
    corr_head_kernel<<<128, 256, CORR_SMEM>>>(G, Wcorr, bcorr, cv);

    // 5) cat conv3x3
    const int CAT_SMEM = (40800 + 5184) * 4;     // 183936 B
    cudaFuncSetAttribute(cat_head_kernel, cudaFuncAttributeMaxDynamicSharedMemorySize, CAT_SMEM);
    cat_head_kernel<<<128, 256, CAT_SMEM>>>(F, Wcat, bcat, tv);

    // 6) MLP heads + final linear -> [128,2]
    mlp_kernel<<<128, 256>>>(cv, tv, cf_w1, cf_b1, cf_w2, cf_b2,
                             ccf_w1, ccf_b1, ccf_w2, ccf_b2,
                             Wout, bout, (float*)d_out);
}

// round 7
// speedup vs baseline: 2.0292x; 2.0164x over previous
#include <cuda_runtime.h>
#include <cuda_bf16.h>
#include <cstdint>
#include <cstddef>

#define NPIX 200

// ---- gmem scratch (static; zero-initialized at load — pad rows rely on it) --
__device__ __align__(16) uint8_t g_wh[3u*4*16*10240];          //  2 MB
__device__ __align__(16) uint8_t g_wl[3u*4*16*10240];
__device__ __align__(16) uint8_t g_finh[3u*128*16*17920];      // 110 MB
__device__ __align__(16) uint8_t g_finl[3u*128*16*17920];
__device__ __align__(16) uint8_t g_fouth[3u*128*16*20480];     // 126 MB
__device__ __align__(16) uint8_t g_foutl[3u*128*16*20480];
__device__ float g_gram[3u*128*200*200];                       //  61 MB
__device__ float g_corrvec[128*600];
__device__ float g_catvec[128*600];

// smem plan for GEMM: stage p at p*56320: AH(10240) AL(10240) BH(17920) BL(17920)
#define STAGE_B   56320
#define SM_CTRL   112640
#define GEMM_SMEM (SM_CTRL + 64)

__device__ __forceinline__ uint32_t smem_u32(const void* p) {
    uint32_t r;
    asm("{ .reg .u64 t; cvta.to.shared.u64 t, %1; cvt.u32.u64 %0, t; }" : "=r"(r) : "l"(p));
    return r;
}
#define MBAR_INIT(a, c) asm volatile("mbarrier.init.shared.b64 [%0], %1;" :: "r"(a), "r"(c) : "memory")
#define MBAR_EXPECT(a, n) asm volatile("mbarrier.arrive.expect_tx.shared.b64 _, [%0], %1;" :: "r"(a), "r"(n) : "memory")
#define MBAR_ARRIVE(a) asm volatile("mbarrier.arrive.shared.b64 _, [%0];" :: "r"(a) : "memory")
#define MBAR_WAIT(a, ph) \
    asm volatile("{\n\t.reg .pred P;\n\tW_%=:\n\t" \
                 "mbarrier.try_wait.parity.acquire.cta.shared::cta.b64 P, [%0], %1, 0x989680;\n\t" \
                 "@!P bra W_%=;\n\t}" :: "r"(a), "r"(ph) : "memory")
#define BULK_G2S(dst, src, bytes, mbar) \
    asm volatile("cp.async.bulk.shared::cluster.global.mbarrier::complete_tx::bytes [%0], [%1], %2, [%3];" \
                 :: "r"(dst), "l"(src), "r"(bytes), "r"(mbar) : "memory")

__device__ __forceinline__ void ldsm4(uint32_t* r, uint32_t a) {
    asm volatile("ldmatrix.sync.aligned.m8n8.x4.shared.b16 {%0,%1,%2,%3}, [%4];"
        : "=r"(r[0]), "=r"(r[1]), "=r"(r[2]), "=r"(r[3]) : "r"(a));
}
__device__ __forceinline__ void ldsm2(uint32_t* r, uint32_t a) {
    asm volatile("ldmatrix.sync.aligned.m8n8.x2.shared.b16 {%0,%1}, [%2];"
        : "=r"(r[0]), "=r"(r[1]) : "r"(a));
}
__device__ __forceinline__ void mma16816(float* c, const uint32_t* a, const uint32_t* b) {
    asm volatile("mma.sync.aligned.m16n8k16.row.col.f32.bf16.bf16.f32 "
        "{%0,%1,%2,%3}, {%4,%5,%6,%7}, {%8,%9}, {%0,%1,%2,%3};"
        : "+f"(c[0]), "+f"(c[1]), "+f"(c[2]), "+f"(c[3])
        : "r"(a[0]), "r"(a[1]), "r"(a[2]), "r"(a[3]), "r"(b[0]), "r"(b[1]));
}
__device__ __forceinline__ void pack8(const float* v, uint4& h, uint4& l) {
    __align__(16) __nv_bfloat16 hb[8], lb[8];
#pragma unroll
    for (int u = 0; u < 8; u++) {
        hb[u] = __float2bfloat16_rn(v[u]);
        lb[u] = __float2bfloat16_rn(v[u] - __bfloat162float(hb[u]));
    }
    h = *reinterpret_cast<uint4*>(hb);
    l = *reinterpret_cast<uint4*>(lb);
}
__device__ __forceinline__ float2 bf2f(uint32_t u) {
    __nv_bfloat162 h = *reinterpret_cast<__nv_bfloat162*>(&u);
    return __bfloat1622float2(h);
}

// ---- weights W[m][k] fp32 -> hi/lo bf16, [t][mt][slab16][row128][40 halves] --
__global__ __launch_bounds__(256) void convert_w_kernel(
    const float* __restrict__ Wa, const float* __restrict__ Wb, const float* __restrict__ Wc,
    uint8_t* __restrict__ oh, uint8_t* __restrict__ ol)
{
    int idx = blockIdx.x * 256 + threadIdx.x;   // 3*512*64 = 98304
    int t = idx / 32768, r = idx - t * 32768;
    int m = r >> 6, g8 = r & 63;
    const float* W = (t == 0) ? Wa : ((t == 1) ? Wb : Wc);
    float v[8];
#pragma unroll
    for (int u = 0; u < 8; u++) v[u] = W[m * 512 + g8 * 8 + u];
    uint4 vh, vl; pack8(v, vh, vl);
    int mt = m >> 7, mr = m & 127, slab = g8 >> 2, c8 = g8 & 3;
    size_t off = ((size_t)(t * 4 + mt) * 16 + slab) * 10240 + mr * 80 + c8 * 16;
    *(uint4*)(oh + off) = vh;
    *(uint4*)(ol + off) = vl;
}

// ---- input feats [b][c][p] -> transposed [t][b][slab16][row p(224 pad)][40] --
__global__ __launch_bounds__(256) void convert_feat_kernel(
    const float* __restrict__ f1, const float* __restrict__ f2, const float* __restrict__ f3,
    uint8_t* __restrict__ oh, uint8_t* __restrict__ ol)
{
    __shared__ float s[32 * 201];
    const int b = blockIdx.x, t = blockIdx.y, tid = threadIdx.x;
    const float* F = ((t == 0) ? f1 : ((t == 1) ? f2 : f3)) + (size_t)b * 102400;
    uint8_t* obh = oh + ((size_t)t * 128 + b) * 286720;
    uint8_t* obl = ol + ((size_t)t * 128 + b) * 286720;
    for (int c = 0; c < 16; c++) {          // chunk c == slab c (32 channels)
        __syncthreads();
        for (int e = tid; e < 32 * 200; e += 256) {
            int kk = e / 200, n = e - kk * 200;
            s[kk * 201 + n] = F[(size_t)(c * 32 + kk) * 200 + n];
        }
        __syncthreads();
        for (int i = tid; i < 800; i += 256) {
            int p = i >> 2, g8 = i & 3;
            float v[8];
#pragma unroll
            for (int u = 0; u < 8; u++) v[u] = s[(g8 * 8 + u) * 201 + p];
            uint4 vh, vl; pack8(v, vh, vl);
            size_t off = (size_t)c * 17920 + p * 80 + g8 * 16;
            *(uint4*)(obh + off) = vh;
            *(uint4*)(obl + off) = vl;
        }
    }
}

// ---- hi/lo split bf16 GEMM via mma.sync, bulk-copy double-buffered ----------
// MODE0 conv1x1: C[m,p] = W·F + bias -> transposed bf16 hi/lo slab output
// MODE1 gram:    C[p1,p2] -> fp32 G
template <int MODE>
__global__ __launch_bounds__(256) void gemm_mma_kernel(
    const uint8_t* __restrict__ Ah, const uint8_t* __restrict__ Al,
    const uint8_t* __restrict__ Bh, const uint8_t* __restrict__ Bl,
    const float* __restrict__ b0, const float* __restrict__ b1, const float* __restrict__ b2,
    float* __restrict__ G, uint8_t* __restrict__ Oh, uint8_t* __restrict__ Ol)
{
    extern __shared__ __align__(128) uint8_t smem[];
    const int tid = threadIdx.x;
    const int mt = blockIdx.x, b = blockIdx.y, z = blockIdx.z;
    const uint32_t sb = smem_u32(smem);
    const int warp = tid >> 5, lane = tid & 31;
    const int warpM = warp & 1, warpN = warp >> 1;

    const uint32_t FULL = sb + SM_CTRL, CONS = sb + SM_CTRL + 16;
    if (tid == 0) {
        MBAR_INIT(FULL, 1);     MBAR_INIT(FULL + 8, 1);
        MBAR_INIT(CONS, 256);   MBAR_INIT(CONS + 8, 256);
    }
    __syncthreads();

    const uint8_t *pAh, *pAl, *pBh, *pBl;
    size_t aStep, bStep;
    if (MODE == 0) {
        size_t ao = (size_t)(z * 4 + mt) * 163840;
        size_t bo = (size_t)(z * 128 + b) * 286720;
        pAh = Ah + ao; pAl = Al + ao; pBh = Bh + bo; pBl = Bl + bo;
        aStep = 10240; bStep = 17920;
    } else {
        int pa = (z == 2) ? 1 : 0, pb = (z == 0) ? 1 : 2;
        size_t ao = (size_t)(pa * 128 + b) * 327680 + (size_t)mt * 10240;
        size_t bo = (size_t)(pb * 128 + b) * 327680;
        pAh = Ah + ao; pAl = Al + ao; pBh = Bh + bo; pBl = Bl + bo;
        aStep = 20480; bStep = 20480;
    }

    float c[4][7][4];
#pragma unroll
    for (int i = 0; i < 4; i++)
#pragma unroll
        for (int j = 0; j < 7; j++)
#pragma unroll
            for (int k = 0; k < 4; k++) c[i][j][k] = 0.f;

    int phF[2] = {0, 0}, phC[2] = {0, 0};
    for (int s = 0; s < 16; s++) {
        const int p = s & 1;
        const uint32_t st = sb + p * STAGE_B;
        if (tid == 0) {
            if (s >= 2) { MBAR_WAIT(CONS + p * 8, phC[p]); phC[p] ^= 1; }
            MBAR_EXPECT(FULL + p * 8, STAGE_B);
            BULK_G2S(st,         pAh + (size_t)s * aStep, 10240, FULL + p * 8);
            BULK_G2S(st + 10240, pAl + (size_t)s * aStep, 10240, FULL + p * 8);
            BULK_G2S(st + 20480, pBh + (size_t)s * bStep, 17920, FULL + p * 8);
            BULK_G2S(st + 38400, pBl + (size_t)s * bStep, 17920, FULL + p * 8);
        }
        MBAR_WAIT(FULL + p * 8, phF[p]); phF[p] ^= 1;

        const uint32_t aBase = st + (warpM * 64 + (lane & 15)) * 80 + (lane & 16);
        const uint32_t bBase = st + 20480 + (warpN * 56 + (lane & 7)) * 80 + (lane & 8) * 2;
#pragma unroll
        for (int ks = 0; ks < 2; ks++) {
            const uint32_t kb = ks * 32;
            uint32_t afh[4][4], afl[4][4];
#pragma unroll
            for (int mi = 0; mi < 4; mi++) {
                ldsm4(afh[mi], aBase + mi * 1280 + kb);
                ldsm4(afl[mi], aBase + 10240 + mi * 1280 + kb);
            }
#pragma unroll
            for (int ni = 0; ni < 7; ni++) {
                uint32_t bfh[2], bfl[2];
                ldsm2(bfh, bBase + ni * 640 + kb);
                ldsm2(bfl, bBase + 17920 + ni * 640 + kb);
#pragma unroll
                for (int mi = 0; mi < 4; mi++) {
                    mma16816(c[mi][ni], afh[mi], bfh);
                    mma16816(c[mi][ni], afh[mi], bfl);
                    mma16816(c[mi][ni], afl[mi], bfh);
                }
            }
        }
        MBAR_ARRIVE(CONS + p * 8);
    }
    __syncthreads();

    if (MODE == 0) {
        const float* bias = (z == 0) ? b0 : ((z == 1) ? b1 : b2);
        __nv_bfloat16* sH = reinterpret_cast<__nv_bfloat16*>(smem);       // [p<200][m128]
        __nv_bfloat16* sL = sH + 25600;
#pragma unroll
        for (int mi = 0; mi < 4; mi++) {
            const int m0 = warpM * 64 + mi * 16 + (lane >> 2);
            const float bv0 = __ldg(bias + mt * 128 + m0);
            const float bv1 = __ldg(bias + mt * 128 + m0 + 8);
#pragma unroll
            for (int ni = 0; ni < 7; ni++) {
                const int p0 = warpN * 56 + ni * 8 + (lane & 3) * 2;
                if (p0 >= 200) continue;
                float v[4] = {c[mi][ni][0] + bv0, c[mi][ni][1] + bv0,
                              c[mi][ni][2] + bv1, c[mi][ni][3] + bv1};
                const int mA = m0, mB = m0 + 8;
#pragma unroll
                for (int q = 0; q < 4; q++) {
                    const int pp = p0 + (q & 1), mm = (q < 2) ? mA : mB;
                    __nv_bfloat16 h = __float2bfloat16_rn(v[q]);
                    sH[pp * 128 + mm] = h;
                    sL[pp * 128 + mm] = __float2bfloat16_rn(v[q] - __bfloat162float(h));
                }
            }
        }
        __syncthreads();
        uint8_t* ohB = Oh + ((size_t)(z * 128 + b) * 16 + mt * 4) * 20480;
        uint8_t* olB = Ol + ((size_t)(z * 128 + b) * 16 + mt * 4) * 20480;
        for (int g = tid; g < 3200; g += 256) {
            int pp = g >> 4, o = g & 15, q = o >> 2, oo = o & 3;
            uint32_t so = (pp * 128 + q * 32 + oo * 8) * 2;
            size_t dof = (size_t)q * 20480 + pp * 80 + oo * 16;
            *(uint4*)(ohB + dof) = *(uint4*)((uint8_t*)sH + so);
            *(uint4*)(olB + dof) = *(uint4*)((uint8_t*)sL + so);
        }
    } else {
        float* Gb = G + ((size_t)z * 128 + b) * 40000;
#pragma unroll
        for (int mi = 0; mi < 4; mi++) {
            const int m0 = mt * 128 + warpM * 64 + mi * 16 + (lane >> 2);
#pragma unroll
            for (int ni = 0; ni < 7; ni++) {
                const int n0 = warpN * 56 + ni * 8 + (lane & 3) * 2;
                if (n0 >= 200) continue;
                if (m0 < 200)
                    *(float2*)(Gb + (size_t)m0 * 200 + n0) = make_float2(c[mi][ni][0], c[mi][ni][1]);
                if (m0 + 8 < 200)
                    *(float2*)(Gb + (size_t)(m0 + 8) * 200 + n0) = make_float2(c[mi][ni][2], c[mi][ni][3]);
            }
        }
    }
}

// ---- corr head: gather from Gram + leaky + conv3x3 + relu -------------------
__global__ __launch_bounds__(256)
void corr_head_kernel(const float* __restrict__ Gram, const float* __restrict__ Wcorr,
                      const float* __restrict__ bcorr, float* __restrict__ corrvec)
{
    extern __shared__ float sh[];
    float* sG = sh;
    float* sW = sh + 40000;
    const int b = blockIdx.x, tid = threadIdx.x;
    const int y = tid / 20, x = tid - y * 20;
    float acc0 = 0.f, acc1 = 0.f, acc2 = 0.f;

    for (int pair = 0; pair < 3; pair++) {
        __syncthreads();
        const float4* G4 = reinterpret_cast<const float4*>(Gram + ((size_t)pair * 128 + b) * 40000);
        float4* sG4 = reinterpret_cast<float4*>(sG);
        for (int i = tid; i < 10000; i += 256) sG4[i] = G4[i];
        for (int i = tid; i < 11907; i += 256) {
            int o = i / 3969, r = i - o * 3969;
            sW[i] = Wcorr[o * 11907 + pair * 3969 + r];
        }
        __syncthreads();
        if (tid < NPIX) {
            for (int ky = 0; ky < 3; ky++) {
                int sy = y + ky - 1;
                if ((unsigned)sy >= 10u) continue;
                for (int kx = 0; kx < 3; kx++) {
                    int sx = x + kx - 1;
                    if ((unsigned)sx >= 20u) continue;
                    const float* grow0 = sG + (sy * 20 + sx) * 200;
                    const int tap = ky * 3 + kx;
                    const int dyi0 = (21 - sy) >> 1, dxi0 = (21 - sx) >> 1;
                    const int p2y0 = sy + 2 * dyi0 - 20, p2x0 = sx + 2 * dxi0 - 20;
                    for (int iy = 0; iy < 5; iy++) {
                        const float* grow = grow0 + (p2y0 + 2 * iy) * 20 + p2x0;
                        const float* wrow = sW + ((dyi0 + iy) * 21 + dxi0) * 9 + tap;
#pragma unroll
                        for (int ix = 0; ix < 10; ix++) {
                            float g = grow[2 * ix] * (1.f / 512.f);
                            float v = g > 0.f ? g : 0.1f * g;
                            acc0 += v * wrow[ix * 9];
                            acc1 += v * wrow[3969 + ix * 9];
                            acc2 += v * wrow[7938 + ix * 9];
                        }
                    }
                }
            }
        }
    }
    if (tid < NPIX) {
        corrvec[b * 600 + tid]       = fmaxf(acc0 + bcorr[0], 0.f);
        corrvec[b * 600 + 200 + tid] = fmaxf(acc1 + bcorr[1], 0.f);
        corrvec[b * 600 + 400 + tid] = fmaxf(acc2 + bcorr[2], 0.f);
    }
}

// ---- cat head: conv3x3 over concat(f1,f2,f3) from hi/lo slab layout ---------
__global__ __launch_bounds__(256)
void cat_head_kernel(const uint8_t* __restrict__ Fh, const uint8_t* __restrict__ Fl,
                     const float* __restrict__ Wcat, const float* __restrict__ bcat,
                     float* __restrict__ catvec)
{
    extern __shared__ float sh[];
    float* sF = sh;             // [(t*200+p)*68 + c]
    float* sW = sh + 40800;
    const int b = blockIdx.x, tid = threadIdx.x;
    const int y = tid / 20, x = tid - y * 20;
    float acc0 = 0.f, acc1 = 0.f, acc2 = 0.f;

    for (int cc = 0; cc < 512; cc += 64) {
        __syncthreads();
        for (int g = tid; g < 4800; g += 256) {
            int t = g / 1600, r = g - t * 1600, p = r >> 3, g8 = r & 7;
            int slab = (cc >> 5) + (g8 >> 2);
            size_t base = (((size_t)t * 128 + b) * 16 + slab) * 20480 + p * 80 + (g8 & 3) * 16;
            uint4 vh = *(const uint4*)(Fh + base);
            uint4 vl = *(const uint4*)(Fl + base);
            float* d = &sF[(t * 200 + p) * 68 + g8 * 8];
            float2 a0 = bf2f(vh.x), c0 = bf2f(vl.x); d[0] = a0.x + c0.x; d[1] = a0.y + c0.y;
            float2 a1 = bf2f(vh.y), c1 = bf2f(vl.y); d[2] = a1.x + c1.x; d[3] = a1.y + c1.y;
            float2 a2 = bf2f(vh.z), c2 = bf2f(vl.z); d[4] = a2.x + c2.x; d[5] = a2.y + c2.y;
            float2 a3 = bf2f(vh.w), c3 = bf2f(vl.w); d[6] = a3.x + c3.x; d[7] = a3.y + c3.y;
        }
        for (int i = tid; i < 5184; i += 256) {
            int o = i / 1728, r = i - o * 1728, t = r / 576, r2 = r - t * 576;
            int tap = r2 >> 6, cch = r2 & 63;
            sW[i] = Wcat[(size_t)(o * 1536 + t * 512 + cc + cch) * 9 + tap];
        }
        __syncthreads();
        if (tid < NPIX) {
            for (int t = 0; t < 3; t++)
                for (int ky = 0; ky < 3; ky++) {
                    int sy = y + ky - 1;
                    if ((unsigned)sy >= 10u) continue;
                    for (int kx = 0; kx < 3; kx++) {
                        int sx = x + kx - 1;
                        if ((unsigned)sx >= 20u) continue;
                        const float4* v4 = reinterpret_cast<const float4*>(sF + (t * 200 + sy * 20 + sx) * 68);
                        int tap = ky * 3 + kx;
                        const float4* w0 = reinterpret_cast<const float4*>(sW + (t * 9 + tap) * 64);
                        const float4* w1 = reinterpret_cast<const float4*>(sW + 1728 + (t * 9 + tap) * 64);
                        const float4* w2 = reinterpret_cast<const float4*>(sW + 3456 + (t * 9 + tap) * 64);
#pragma unroll
                        for (int c4 = 0; c4 < 16; c4++) {
                            float4 v = v4[c4];
                            float4 a = w0[c4], bq = w1[c4], cq = w2[c4];
                            acc0 += v.x * a.x + v.y * a.y + v.z * a.z + v.w * a.w;
                            acc1 += v.x * bq.x + v.y * bq.y + v.z * bq.z + v.w * bq.w;
                            acc2 += v.x * cq.x + v.y * cq.y + v.z * cq.z + v.w * cq.w;
                        }
                    }
                }
        }
    }
    if (tid < NPIX) {
        catvec[b * 600 + tid]       = acc0 + bcat[0];
        catvec[b * 600 + 200 + tid] = acc1 + bcat[1];
        catvec[b * 600 + 400 + tid] = acc2 + bcat[2];
    }
}

// ---- MLP heads + final linear ------------------------------------------------
__global__ __launch_bounds__(256)
void mlp_kernel(const float* __restrict__ corrvec, const float* __restrict__ catvec,
                const float* __restrict__ cf_w1, const float* __restrict__ cf_b1,
                const float* __restrict__ cf_w2, const float* __restrict__ cf_b2,
                const float* __restrict__ ccf_w1, const float* __restrict__ ccf_b1,
                const float* __restrict__ ccf_w2, const float* __restrict__ ccf_b2,
                const float* __restrict__ Wout, const float* __restrict__ bout,
                float* __restrict__ out)
{
    __shared__ float sx[600];
    __shared__ float h1[256];
    __shared__ float h2[2][128];
    const int b = blockIdx.x, tid = threadIdx.x;

    for (int path = 0; path < 2; path++) {
        const float* xv = (path == 0 ? corrvec : catvec) + b * 600;
        const float* w1 = path == 0 ? cf_w1 : ccf_w1;
        const float* b1 = path == 0 ? cf_b1 : ccf_b1;
        const float* w2 = path == 0 ? cf_w2 : ccf_w2;
        const float* b2 = path == 0 ? cf_b2 : ccf_b2;
        __syncthreads();
        for (int i = tid; i < 600; i += 256) sx[i] = xv[i];
        __syncthreads();
        {
            float s = b1[tid];
            const float4* wr = reinterpret_cast<const float4*>(w1 + (size_t)tid * 600);
#pragma unroll 4
            for (int k = 0; k < 150; k++) {
                float4 w = wr[k];
                s += w.x * sx[4*k] + w.y * sx[4*k+1] + w.z * sx[4*k+2] + w.w * sx[4*k+3];
            }
            h1[tid] = fmaxf(s, 0.f);
        }
        __syncthreads();
        if (tid < 128) {
            float s = b2[tid];
            const float4* wr = reinterpret_cast<const float4*>(w2 + (size_t)tid * 256);
#pragma unroll 4
            for (int k = 0; k < 64; k++) {
                float4 w = wr[k];
                s += w.x * h1[4*k] + w.y * h1[4*k+1] + w.z * h1[4*k+2] + w.w * h1[4*k+3];
            }
            h2[path][tid] = fmaxf(s, 0.f);
        }
    }
    __syncthreads();
    if (tid < 2) {
        float s = bout[tid];
        const float* wr = Wout + tid * 256;
        for (int i = 0; i < 128; i++)
            s += h2[0][i] * wr[i] + h2[1][i] * wr[128 + i];
        out[b * 2 + tid] = s;
    }
}

// ---- launch -------------------------------------------------------------------
extern "C" void kernel_launch(void* const* d_in, const int* in_sizes, int n_in,
                              void* d_out, int out_size)
{
    (void)in_sizes; (void)n_in; (void)out_size;
    const float* feat1 = (const float*)d_in[0];
    const float* feat2 = (const float*)d_in[1];
    const float* feat3 = (const float*)d_in[2];
    const float* Wa = (const float*)d_in[3];   const float* ba = (const float*)d_in[4];
    const float* Wb = (const float*)d_in[5];   const float* bb = (const float*)d_in[6];
    const float* Wc = (const float*)d_in[7];   const float* bc = (const float*)d_in[8];
    const float* Wcorr = (const float*)d_in[9];  const float* bcorr = (const float*)d_in[10];
    const float* Wcat = (const float*)d_in[11];  const float* bcat = (const float*)d_in[12];
    const float* cf_w1 = (const float*)d_in[13]; const float* cf_b1 = (const float*)d_in[14];
    const float* cf_w2 = (const float*)d_in[15]; const float* cf_b2 = (const float*)d_in[16];
    const float* ccf_w1 = (const float*)d_in[17]; const float* ccf_b1 = (const float*)d_in[18];
    const float* ccf_w2 = (const float*)d_in[19]; const float* ccf_b2 = (const float*)d_in[20];
    const float* Wout = (const float*)d_in[21];  const float* bout = (const float*)d_in[22];

    uint8_t *wh, *wl, *fih, *fil, *foh, *fol;
    float *G, *cv, *tv;
    cudaGetSymbolAddress((void**)&wh,  g_wh);
    cudaGetSymbolAddress((void**)&wl,  g_wl);
    cudaGetSymbolAddress((void**)&fih, g_finh);
    cudaGetSymbolAddress((void**)&fil, g_finl);
    cudaGetSymbolAddress((void**)&foh, g_fouth);
    cudaGetSymbolAddress((void**)&fol, g_foutl);
    cudaGetSymbolAddress((void**)&G,   g_gram);
    cudaGetSymbolAddress((void**)&cv,  g_corrvec);
    cudaGetSymbolAddress((void**)&tv,  g_catvec);

    cudaFuncSetAttribute(gemm_mma_kernel<0>, cudaFuncAttributeMaxDynamicSharedMemorySize, GEMM_SMEM);
    cudaFuncSetAttribute(gemm_mma_kernel<1>, cudaFuncAttributeMaxDynamicSharedMemorySize, GEMM_SMEM);

    convert_w_kernel<<<384, 256>>>(Wa, Wb, Wc, wh, wl);
    convert_feat_kernel<<<dim3(128, 3), 256>>>(feat1, feat2, feat3, fih, fil);

    // conv1x1 per (mtile4, batch, tensor)
    gemm_mma_kernel<0><<<dim3(4, 128, 3), 256, GEMM_SMEM>>>(
        wh, wl, fih, fil, ba, bb, bc, nullptr, foh, fol);

    // Gram per (mtile2, batch, pair)
    gemm_mma_kernel<1><<<dim3(2, 128, 3), 256, GEMM_SMEM>>>(
        foh, fol, foh, fol, nullptr, nullptr, nullptr, G, nullptr, nullptr);

    const int CORR_SMEM = (40000 + 11907) * 4;
    cudaFuncSetAttribute(corr_head_kernel, cudaFuncAttributeMaxDynamicSharedMemorySize, CORR_SMEM);
    corr_head_kernel<<<128, 256, CORR_SMEM>>>(G, Wcorr, bcorr, cv);

    const int CAT_SMEM = (40800 + 5184) * 4;
    cudaFuncSetAttribute(cat_head_kernel, cudaFuncAttributeMaxDynamicSharedMemorySize, CAT_SMEM);
    cat_head_kernel<<<128, 256, CAT_SMEM>>>(foh, fol, Wcat, bcat, tv);

    mlp_kernel<<<128, 256>>>(cv, tv, cf_w1, cf_b1, cf_w2, cf_b2,
                             ccf_w1, ccf_b1, ccf_w2, ccf_b2, Wout, bout, (float*)d_out);
}